// round 14
// baseline (speedup 1.0000x reference)
#include <cuda_runtime.h>
#include <cuda_bf16.h>
#include <cuda_fp8.h>
#include <math.h>
#include <stdint.h>

// Problem constants (fixed shapes: x [8,512,64,64] fp32, mask [64,64] bool)
#define B 8
#define C 512
#define D 256              // C/2
#define N 4096             // 64*64
#define OUTC 768           // 3*D

// ---- device scratch (no allocation allowed) ----
__device__ float g_invnorm[B * N];
__device__ int   g_kidx[N];     // known (unmasked) pixel indices, ascending
__device__ int   g_qidx[N];     // hole (masked) pixel indices, ascending
__device__ int   g_rank[N];     // pixel -> hole rank, or -1 if known
__device__ int   g_counts[2];   // [0]=nKnown, [1]=nHole

// packed e4m3 operands:
//   g_Q, g_K: [b][row][256] row-major (row = compact index), 1 B/elem
//   g_V:      [b][d][key] TRANSPOSED, row stride 4096, 1 B/elem
__device__ __align__(256) unsigned char g_K[(size_t)B * 4096 * 256];
__device__ __align__(256) unsigned char g_Q[(size_t)B * 4096 * 256];
__device__ __align__(256) unsigned char g_V[(size_t)B * 256 * 4096];

// split-K partials: O [split][b][d][q] (d-major), L [split][b][q]
__device__ __align__(256) float g_pO[(size_t)2 * B * 256 * 4096];
__device__ float g_pL[2 * B * 4096];

// ============================================================
// PTX helpers
// ============================================================
__device__ __forceinline__ uint32_t smaddr(const void* p) {
    return (uint32_t)__cvta_generic_to_shared(p);
}
__device__ __forceinline__ void ldsm4(uint32_t* r, uint32_t a) {
    asm volatile("ldmatrix.sync.aligned.m8n8.x4.shared.b16 {%0,%1,%2,%3}, [%4];"
        : "=r"(r[0]), "=r"(r[1]), "=r"(r[2]), "=r"(r[3]) : "r"(a));
}
// fp8 m16n8k32: A e4m3 (4 regs), B e4m3 (2 regs), C/D f32 (4 regs)
__device__ __forceinline__ void mma_fp8(float* c, const uint32_t* a, uint32_t b0, uint32_t b1) {
    asm volatile("mma.sync.aligned.m16n8k32.row.col.f32.e4m3.e4m3.f32 "
        "{%0,%1,%2,%3}, {%4,%5,%6,%7}, {%8,%9}, {%0,%1,%2,%3};"
        : "+f"(c[0]), "+f"(c[1]), "+f"(c[2]), "+f"(c[3])
        : "r"(a[0]), "r"(a[1]), "r"(a[2]), "r"(a[3]), "r"(b0), "r"(b1));
}
__device__ __forceinline__ void cpasync16(uint32_t s, const void* g) {
    asm volatile("cp.async.cg.shared.global [%0], [%1], 16;" :: "r"(s), "l"(g));
}
__device__ __forceinline__ void cpasync4(uint32_t s, const void* g) {
    asm volatile("cp.async.ca.shared.global [%0], [%1], 4;" :: "r"(s), "l"(g));
}
__device__ __forceinline__ unsigned char f2e4m3(float v) {
    return (unsigned char)__nv_cvt_float_to_fp8(v, __NV_SATFINITE, __NV_E4M3);
}
__device__ __forceinline__ unsigned short f2x2e4m3(float lo, float hi) {
    float2 f2 = make_float2(lo, hi);   // .x -> low byte
    return (unsigned short)__nv_cvt_float2_to_fp8x2(f2, __NV_SATFINITE, __NV_E4M3);
}

// ============================================================
// K0: copy former+latter into out channels [0,512). Shift region
//     [512,768) is written densely by k_reduce.
// ============================================================
__global__ void k_copy(const float4* __restrict__ x4, float4* __restrict__ o4) {
    int i = blockIdx.x * 256 + threadIdx.x;           // < 4194304
    int b = i >> 19;
    int r = i & 524287;
    o4[(size_t)b * (OUTC * N / 4) + r] = x4[i];
}

// ============================================================
// K1: inv-norm of latter per (b, n)
// ============================================================
__global__ void k_invnorm(const float* __restrict__ x) {
    int b = blockIdx.y;
    int n = blockIdx.x * 128 + threadIdx.x;
    const float* p = x + ((size_t)b * C + D) * N + n;
    float s = 0.f;
#pragma unroll 8
    for (int d = 0; d < D; ++d) {
        float v = p[(size_t)d * N];
        s = fmaf(v, v, s);
    }
    g_invnorm[b * N + n] = 1.0f / (sqrtf(s) + 1e-8f);
}

// ============================================================
// K2: build compact index lists + pixel->rank table
// ============================================================
__global__ void k_build_lists(const unsigned char* __restrict__ mask8) {
    __shared__ int cK[256], cH[256];
    __shared__ int byteEvidence;
    const int t = threadIdx.x;
    if (t == 0) byteEvidence = 0;
    __syncthreads();

    const unsigned int* m32 = (const unsigned int*)mask8;
    int bad = 0;
    for (int w = t; w < 1024; w += 256) {
        unsigned int v = m32[w];
        if (v != 0u && v != 1u && v != 0x3F800000u) bad = 1;
    }
    if (bad) byteEvidence = 1;
    __syncthreads();
    const bool byteMode = (byteEvidence != 0);

    const int base = t * 16;
    int ck = 0, ch = 0;
#pragma unroll
    for (int e = 0; e < 16; ++e) {
        int m = base + e;
        bool f = byteMode ? (mask8[m] != 0) : (m32[m] != 0u);
        if (f) ch++; else ck++;
    }
    cK[t] = ck; cH[t] = ch;
    __syncthreads();
    for (int off = 1; off < 256; off <<= 1) {
        int a = (t >= off) ? cK[t - off] : 0;
        int b2 = (t >= off) ? cH[t - off] : 0;
        __syncthreads();
        cK[t] += a; cH[t] += b2;
        __syncthreads();
    }
    int kb = cK[t] - ck;
    int hb = cH[t] - ch;
#pragma unroll
    for (int e = 0; e < 16; ++e) {
        int m = base + e;
        bool f = byteMode ? (mask8[m] != 0) : (m32[m] != 0u);
        if (f) { g_rank[m] = hb; g_qidx[hb++] = m; }
        else   { g_rank[m] = -1; g_kidx[kb++] = m; }
    }
    if (t == 255) { g_counts[0] = cK[255]; g_counts[1] = cH[255]; }
}

// ============================================================
// K3: pack gathered operands to e4m3.
//   which 0: K rows [key][256]; which 2: Q rows [q][256]
//   which 1: V TRANSPOSED [d][key] (stride 4096)
//   Gather via cp.async.ca 4B (deep MLP, verified R10).
// ============================================================
#define PACK_SMEM (256 * 65 * 4)   // 66560 B

__global__ void k_pack(const float* __restrict__ x) {
    extern __shared__ float ts[];            // [256][65]
    __shared__ int   sIdx[64];
    __shared__ float sSc[64];
    const int b = blockIdx.y, which = blockIdx.z;
    const int row0 = blockIdx.x * 64;
    const int t = threadIdx.x;

    const int cnt = (which == 2) ? g_counts[1] : g_counts[0];
    if (row0 >= ((cnt + 63) & ~63)) return;

    const int* list = (which == 2) ? g_qidx : g_kidx;
    const float* src = (which == 1) ? (x + (size_t)b * C * N)
                                    : (x + ((size_t)b * C + D) * N);

    if (t < 64) {
        int r = row0 + t;
        int m = (r < cnt) ? list[r] : -1;
        sIdx[t] = (m >= 0) ? m : 0;
        sSc[t] = (m >= 0) ? ((which == 1) ? 1.f : g_invnorm[b * N + m]) : 0.f;
    }
    __syncthreads();

    const uint32_t tsb = smaddr(ts);
#pragma unroll 16
    for (int j = 0; j < 64; ++j) {
        int idx = t + 256 * j;
        int row = idx & 63, dd = idx >> 6;
        cpasync4(tsb + (uint32_t)((dd * 65 + row) << 2),
                 src + (size_t)dd * N + sIdx[row]);
    }
    asm volatile("cp.async.commit_group;");
    asm volatile("cp.async.wait_group 0;" ::: "memory");
    __syncthreads();

    if (which == 1) {
        // V^T: [d][key]
        unsigned char* dstV = g_V + (size_t)b * 256 * 4096;
#pragma unroll 16
        for (int j = 0; j < 64; ++j) {
            int idx = t + 256 * j;
            int key = idx & 63, d = idx >> 6;
            dstV[(size_t)d * 4096 + row0 + key] = f2e4m3(ts[d * 65 + key] * sSc[key]);
        }
    } else {
        unsigned char* dst = (which == 0 ? g_K : g_Q) + ((size_t)b * 4096 + row0) * 256;
#pragma unroll 16
        for (int j = 0; j < 64; ++j) {
            dst[(size_t)j * 256 + t] = f2e4m3(ts[t * 65 + j] * sSc[j]);
        }
    }
}

// ============================================================
// K4: FP8 mma flash attention, split-K=2.
//   CTA = 64 hole queries x 1 batch x 1 split. 4 warps, 128 thr,
//   2 CTAs/SM. BK=32. fp8 tiles b16-viewed for ldmatrix.
//   Q A-frags hoisted into registers (loaded once).
//   P tile per warp: 16 rows x 48B pitch, rows addressed WARP-LOCALLY
//   (R13 bug: global row index double-counted the warp offset ->
//    warps 1-3 read uninitialized smem -> e4m3 NaN decode).
// ============================================================
#define SQ_   0          // 64 rows x 256 B
#define SK0_  16384      // 32 rows x 256 B
#define SK1_  24576
#define SV0_  32768      // 256 rows x 48 B pitch (32 B data)
#define SV1_  45056
#define SP_   57344      // 4 warps x 16 rows x 48 B
#define SQN_  66560      // after tsO region (tsO = [0,66560))
#define ATTN_SMEM 66816

__device__ __forceinline__ uint32_t swk(int row, int ch) {  // 256B rows, 16 chunks
    return (uint32_t)((row * 16 + (ch ^ (row & 7))) << 4);
}

__global__ __launch_bounds__(128, 2)
void k_attn() {
    extern __shared__ char smc[];
    const uint32_t sb = smaddr(smc);
    const int t = threadIdx.x;
    const int lane = t & 31, w = t >> 5;       // w in 0..3
    const int b = blockIdx.y, qt = blockIdx.x, split = blockIdx.z;

    const int nKnown = g_counts[0];
    const int nHole  = g_counts[1];
    const int q0 = qt * 64;
    if (q0 >= nHole) return;
    const int nQ = min(64, nHole - q0);

    const int nkt = (nKnown + 31) >> 5;        // BK=32 tiles
    const int h   = (nkt + 1) >> 1;
    const int kt0 = split ? h : 0;
    const int ktE = split ? nkt : h;
    const int L   = ktE - kt0;

    int* sQn = (int*)(smc + SQN_);
    if (t < 64) sQn[t] = (t < nQ) ? g_qidx[q0 + t] : -1;

    const unsigned char* gq  = g_Q + ((size_t)b * 4096 + q0) * 256;
    const unsigned char* gk  = g_K + (size_t)b * 4096 * 256;
    const unsigned char* gvt = g_V + (size_t)b * 256 * 4096;

    // ---- prologue: Q + KV(kt0) in group0; KV(kt0+1) in group1 ----
#pragma unroll 8
    for (int i = t; i < 1024; i += 128) {   // Q: 64 rows x 16 chunks
        int row = i >> 4, ch = i & 15;
        cpasync16(sb + SQ_ + swk(row, ch), gq + row * 256 + ch * 16);
    }
#define LOAD_KV(kt_, kb_, vb_) do { \
    for (int i2 = t; i2 < 512; i2 += 128) { \
        int row = i2 >> 4, ch = i2 & 15; \
        cpasync16((kb_) + swk(row, ch), gk + (size_t)((kt_) * 32 + row) * 256 + ch * 16); \
    } \
    for (int i2 = t; i2 < 512; i2 += 128) { \
        int dd = i2 >> 1, ch = i2 & 1; \
        cpasync16((vb_) + (uint32_t)(dd * 48 + ch * 16), \
                  gvt + (size_t)dd * 4096 + (kt_) * 32 + ch * 16); \
    } \
} while (0)

    if (L > 0) { LOAD_KV(kt0, sb + SK0_, sb + SV0_); asm volatile("cp.async.commit_group;"); }
    if (L > 1) { LOAD_KV(kt0 + 1, sb + SK1_, sb + SV1_); asm volatile("cp.async.commit_group;"); }

    float O[32][4];
#pragma unroll
    for (int i = 0; i < 32; ++i) { O[i][0] = O[i][1] = O[i][2] = O[i][3] = 0.f; }
    float rs0 = 0.f, rs1 = 0.f;
    uint32_t aq[8][4];                          // hoisted Q A-frags (K=256 = 8 k32-steps)

    const int band = w * 16;
    const int r15 = lane & 15, chalf = lane >> 4;
    const int l8 = lane & 7, sel = lane >> 3;
    const int lq = lane >> 2;                   // warp-local P row (0..7)
    const int qr0 = band + lq, qr1 = qr0 + 8;   // global query rows
    const uint32_t pbase = sb + SP_ + w * 768;

    for (int i = 0; i < L; ++i) {
        const int kt = kt0 + i;
        if (i + 1 < L) asm volatile("cp.async.wait_group 1;" ::: "memory");
        else           asm volatile("cp.async.wait_group 0;" ::: "memory");
        __syncthreads();
        const uint32_t smk = sb + ((i & 1) ? SK1_ : SK0_);
        const char* svp = smc + ((i & 1) ? SV1_ : SV0_);

        if (i == 0) {   // Q resident now; load A-frags once
#pragma unroll
            for (int ks = 0; ks < 8; ++ks)
                ldsm4(aq[ks], sb + SQ_ + swk(band + r15, ks * 2 + chalf));
        }

        // ---- S = Q K^T : 16q x 32k, fp8 k32 ----
        float s[4][4];
#pragma unroll
        for (int j = 0; j < 4; ++j) { s[j][0] = s[j][1] = s[j][2] = s[j][3] = 0.f; }
#pragma unroll
        for (int ks = 0; ks < 8; ++ks) {
#pragma unroll
            for (int g = 0; g < 2; ++g) {
                uint32_t bb[4];
                ldsm4(bb, smk + swk(g * 16 + (sel >> 1) * 8 + l8, ks * 2 + (sel & 1)));
                mma_fp8(s[2 * g],     aq[ks], bb[0], bb[1]);
                mma_fp8(s[2 * g + 1], aq[ks], bb[2], bb[3]);
            }
        }

        // ---- P = exp(S-1), mask, rowsum (fp32), quantize -> warp P tile ----
        const int kg = kt * 32 + (lane & 3) * 2;
#pragma unroll
        for (int j = 0; j < 4; ++j) {
            float p0 = __expf(s[j][0] - 1.f), p1 = __expf(s[j][1] - 1.f);
            float p2 = __expf(s[j][2] - 1.f), p3 = __expf(s[j][3] - 1.f);
            int keyg = kg + j * 8;
            if (keyg >= nKnown)     { p0 = 0.f; p2 = 0.f; }
            if (keyg + 1 >= nKnown) { p1 = 0.f; p3 = 0.f; }
            rs0 += p0 + p1;
            rs1 += p2 + p3;
            int boff = j * 8 + (lane & 3) * 2;   // key byte within 32B row
            // WARP-LOCAL rows lq and lq+8 (R13 fix)
            *(unsigned short*)(smc + SP_ + w * 768 + lq * 48 + boff)       = f2x2e4m3(p0, p1);
            *(unsigned short*)(smc + SP_ + w * 768 + (lq + 8) * 48 + boff) = f2x2e4m3(p2, p3);
        }
        __syncwarp();
        uint32_t pa[4];
        ldsm4(pa, pbase + (uint32_t)(r15 * 48 + chalf * 16));

        // ---- O += P V : 16q x 256d, B-frags via conflict-free LDS.32 ----
#pragma unroll
        for (int g = 0; g < 32; ++g) {
            uint32_t voff = (uint32_t)((g * 8 + lq) * 48 + (lane & 3) * 4);
            uint32_t v0 = *(const uint32_t*)(svp + voff);
            uint32_t v1 = *(const uint32_t*)(svp + voff + 16);
            mma_fp8(O[g], pa, v0, v1);
        }

        __syncthreads();   // all warps done with buffer i&1 (incl. P reads)
        if (i + 2 < L) {
            const uint32_t kb_ = sb + ((i & 1) ? SK1_ : SK0_);
            const uint32_t vb_ = sb + ((i & 1) ? SV1_ : SV0_);
            LOAD_KV(kt + 2, kb_, vb_);
            asm volatile("cp.async.commit_group;");
        }
    }

    // ---- rowsum quad-reduce, write partial L ----
    rs0 += __shfl_xor_sync(0xffffffffu, rs0, 1);
    rs0 += __shfl_xor_sync(0xffffffffu, rs0, 2);
    rs1 += __shfl_xor_sync(0xffffffffu, rs1, 1);
    rs1 += __shfl_xor_sync(0xffffffffu, rs1, 2);
    if ((lane & 3) == 0) {
        g_pL[(split * B + b) * 4096 + q0 + qr0] = rs0;
        g_pL[(split * B + b) * 4096 + q0 + qr1] = rs1;
    }

    // ---- transpose O via smem (reuse [0,66560)), coalesced partial store ----
    float* tsO = (float*)smc;    // [256][65]
#pragma unroll
    for (int nt = 0; nt < 32; ++nt) {
        int d0 = nt * 8 + (lane & 3) * 2;
        tsO[d0 * 65 + qr0]       = O[nt][0];
        tsO[(d0 + 1) * 65 + qr0] = O[nt][1];
        tsO[d0 * 65 + qr1]       = O[nt][2];
        tsO[(d0 + 1) * 65 + qr1] = O[nt][3];
    }
    __syncthreads();
    float* po = g_pO + ((size_t)(split * B + b) * 256) * 4096 + q0;
#pragma unroll 8
    for (int j = 0; j < 128; ++j) {
        int idx = t + 128 * j;
        int q = idx & 63, d = idx >> 6;
        po[(size_t)d * 4096 + q] = tsO[d * 65 + q];
    }
}

// ============================================================
// K5: reduce splits + write the ENTIRE shift channel region.
// ============================================================
__global__ void k_reduce(float* __restrict__ out) {
    const int n = blockIdx.x * 256 + threadIdx.x;
    const int d = blockIdx.y;
    const int b = blockIdx.z;
    const int r = g_rank[n];
    float v = 0.f;
    if (r >= 0) {
        float l = g_pL[b * 4096 + r] + g_pL[(B + b) * 4096 + r];
        float o0 = g_pO[((size_t)b * 256 + d) * 4096 + r];
        float o1 = g_pO[((size_t)(B + b) * 256 + d) * 4096 + r];
        v = (o0 + o1) / l;
    }
    out[((size_t)b * OUTC + 2 * D + d) * N + n] = v;
}

// ============================================================
extern "C" void kernel_launch(void* const* d_in, const int* in_sizes, int n_in,
                              void* d_out, int out_size) {
    const float* x = (const float*)d_in[0];
    const unsigned char* mask = (const unsigned char*)d_in[1];
    float* out = (float*)d_out;
    (void)in_sizes; (void)n_in; (void)out_size;

    k_copy<<<(B * C * N / 4) / 256, 256>>>((const float4*)x, (float4*)out);
    k_invnorm<<<dim3(N / 128, B), 128>>>(x);
    k_build_lists<<<1, 256>>>(mask);

    cudaFuncSetAttribute(k_pack, cudaFuncAttributeMaxDynamicSharedMemorySize, PACK_SMEM);
    k_pack<<<dim3(64, B, 3), 256, PACK_SMEM>>>(x);

    cudaFuncSetAttribute(k_attn, cudaFuncAttributeMaxDynamicSharedMemorySize, ATTN_SMEM);
    k_attn<<<dim3(64, B, 2), 128, ATTN_SMEM>>>();

    k_reduce<<<dim3(N / 256, D, B), 256>>>(out);
}

// round 15
// speedup vs baseline: 1.1156x; 1.1156x over previous
#include <cuda_runtime.h>
#include <cuda_bf16.h>
#include <math.h>
#include <stdint.h>

// Problem constants (fixed shapes: x [8,512,64,64] fp32, mask [64,64] bool)
#define B 8
#define C 512
#define D 256              // C/2
#define N 4096             // 64*64
#define OUTC 768           // 3*D

// ---- device scratch (no allocation allowed) ----
__device__ float g_invnorm[B * N];
__device__ int   g_kidx[N];     // known (unmasked) pixel indices, ascending
__device__ int   g_qidx[N];     // hole (masked) pixel indices, ascending
__device__ int   g_rank[N];     // pixel -> hole rank, or -1 if known
__device__ int   g_counts[2];   // [0]=nKnown, [1]=nHole

// packed bf16 operands: [b][row][256] row-major (row = compact index)
__device__ __align__(256) __nv_bfloat16 g_K[(size_t)B * 4096 * 256];
__device__ __align__(256) __nv_bfloat16 g_V[(size_t)B * 4096 * 256];
__device__ __align__(256) __nv_bfloat16 g_Q[(size_t)B * 4096 * 256];

// split-K partials: O [split][b][d][q] (d-major), L [split][b][q]
__device__ __align__(256) float g_pO[(size_t)2 * B * 256 * 4096];
__device__ float g_pL[2 * B * 4096];

// ============================================================
// PTX helpers (bf16 legacy mma — fp8 m16n8k32 measured SLOWER on
// this part in R14; tcgen05 rejected by ptxas target, R8)
// ============================================================
__device__ __forceinline__ uint32_t smaddr(const void* p) {
    return (uint32_t)__cvta_generic_to_shared(p);
}
__device__ __forceinline__ void ldsm4(uint32_t* r, uint32_t a) {
    asm volatile("ldmatrix.sync.aligned.m8n8.x4.shared.b16 {%0,%1,%2,%3}, [%4];"
        : "=r"(r[0]), "=r"(r[1]), "=r"(r[2]), "=r"(r[3]) : "r"(a));
}
__device__ __forceinline__ void ldsm4t(uint32_t* r, uint32_t a) {
    asm volatile("ldmatrix.sync.aligned.m8n8.x4.trans.shared.b16 {%0,%1,%2,%3}, [%4];"
        : "=r"(r[0]), "=r"(r[1]), "=r"(r[2]), "=r"(r[3]) : "r"(a));
}
__device__ __forceinline__ void mma_bf16(float* c, const uint32_t* a, uint32_t b0, uint32_t b1) {
    asm volatile("mma.sync.aligned.m16n8k16.row.col.f32.bf16.bf16.f32 "
        "{%0,%1,%2,%3}, {%4,%5,%6,%7}, {%8,%9}, {%0,%1,%2,%3};"
        : "+f"(c[0]), "+f"(c[1]), "+f"(c[2]), "+f"(c[3])
        : "r"(a[0]), "r"(a[1]), "r"(a[2]), "r"(a[3]), "r"(b0), "r"(b1));
}
__device__ __forceinline__ void cpasync16(uint32_t s, const void* g) {
    asm volatile("cp.async.cg.shared.global [%0], [%1], 16;" :: "r"(s), "l"(g));
}
__device__ __forceinline__ void cpasync4(uint32_t s, const void* g) {
    asm volatile("cp.async.ca.shared.global [%0], [%1], 4;" :: "r"(s), "l"(g));
}
__device__ __forceinline__ uint32_t packbf2(float lo, float hi) {
    __nv_bfloat162 h = __floats2bfloat162_rn(lo, hi);
    return *(uint32_t*)&h;
}

// ============================================================
// K0: copy former+latter into out channels [0,512). Shift region
//     [512,768) is written densely by k_reduce.
// ============================================================
__global__ void k_copy(const float4* __restrict__ x4, float4* __restrict__ o4) {
    int i = blockIdx.x * 256 + threadIdx.x;           // < 4194304
    int b = i >> 19;
    int r = i & 524287;
    o4[(size_t)b * (OUTC * N / 4) + r] = x4[i];
}

// ============================================================
// K1: inv-norm of latter per (b, n)
// ============================================================
__global__ void k_invnorm(const float* __restrict__ x) {
    int b = blockIdx.y;
    int n = blockIdx.x * 128 + threadIdx.x;
    const float* p = x + ((size_t)b * C + D) * N + n;
    float s = 0.f;
#pragma unroll 8
    for (int d = 0; d < D; ++d) {
        float v = p[(size_t)d * N];
        s = fmaf(v, v, s);
    }
    g_invnorm[b * N + n] = 1.0f / (sqrtf(s) + 1e-8f);
}

// ============================================================
// K2: build compact index lists + pixel->rank table
// ============================================================
__global__ void k_build_lists(const unsigned char* __restrict__ mask8) {
    __shared__ int cK[256], cH[256];
    __shared__ int byteEvidence;
    const int t = threadIdx.x;
    if (t == 0) byteEvidence = 0;
    __syncthreads();

    const unsigned int* m32 = (const unsigned int*)mask8;
    int bad = 0;
    for (int w = t; w < 1024; w += 256) {
        unsigned int v = m32[w];
        if (v != 0u && v != 1u && v != 0x3F800000u) bad = 1;
    }
    if (bad) byteEvidence = 1;
    __syncthreads();
    const bool byteMode = (byteEvidence != 0);

    const int base = t * 16;
    int ck = 0, ch = 0;
#pragma unroll
    for (int e = 0; e < 16; ++e) {
        int m = base + e;
        bool f = byteMode ? (mask8[m] != 0) : (m32[m] != 0u);
        if (f) ch++; else ck++;
    }
    cK[t] = ck; cH[t] = ch;
    __syncthreads();
    for (int off = 1; off < 256; off <<= 1) {
        int a = (t >= off) ? cK[t - off] : 0;
        int b2 = (t >= off) ? cH[t - off] : 0;
        __syncthreads();
        cK[t] += a; cH[t] += b2;
        __syncthreads();
    }
    int kb = cK[t] - ck;
    int hb = cH[t] - ch;
#pragma unroll
    for (int e = 0; e < 16; ++e) {
        int m = base + e;
        bool f = byteMode ? (mask8[m] != 0) : (m32[m] != 0u);
        if (f) { g_rank[m] = hb; g_qidx[hb++] = m; }
        else   { g_rank[m] = -1; g_kidx[kb++] = m; }
    }
    if (t == 255) { g_counts[0] = cK[255]; g_counts[1] = cH[255]; }
}

// ============================================================
// K3: pack gathered operands to bf16 row-major [row][256].
//   which: 0=K(norm latter), 1=V(former), 2=Q(norm latter @qidx)
//   Gather via cp.async.ca 4B (deep MLP, verified R10).
// ============================================================
#define PACK_SMEM (256 * 65 * 4)   // 66560 B

__global__ void k_pack(const float* __restrict__ x) {
    extern __shared__ float ts[];            // [256][65]
    __shared__ int   sIdx[64];
    __shared__ float sSc[64];
    const int b = blockIdx.y, which = blockIdx.z;
    const int row0 = blockIdx.x * 64;
    const int t = threadIdx.x;

    const int cnt = (which == 2) ? g_counts[1] : g_counts[0];
    if (row0 >= ((cnt + 63) & ~63)) return;

    const int* list = (which == 2) ? g_qidx : g_kidx;
    const float* src = (which == 1) ? (x + (size_t)b * C * N)
                                    : (x + ((size_t)b * C + D) * N);
    __nv_bfloat16* dst = (which == 0 ? g_K : (which == 1 ? g_V : g_Q))
                         + ((size_t)b * 4096 + row0) * 256;

    if (t < 64) {
        int r = row0 + t;
        int m = (r < cnt) ? list[r] : -1;
        sIdx[t] = (m >= 0) ? m : 0;
        sSc[t] = (m >= 0) ? ((which == 1) ? 1.f : g_invnorm[b * N + m]) : 0.f;
    }
    __syncthreads();

    const uint32_t tsb = smaddr(ts);
#pragma unroll 16
    for (int j = 0; j < 64; ++j) {
        int idx = t + 256 * j;
        int row = idx & 63, dd = idx >> 6;
        cpasync4(tsb + (uint32_t)((dd * 65 + row) << 2),
                 src + (size_t)dd * N + sIdx[row]);
    }
    asm volatile("cp.async.commit_group;");
    asm volatile("cp.async.wait_group 0;" ::: "memory");
    __syncthreads();

#pragma unroll 16
    for (int j = 0; j < 64; ++j) {
        dst[(size_t)j * 256 + t] = __float2bfloat16(ts[t * 65 + j] * sSc[j]);
    }
}

// ============================================================
// K4: bf16 mma flash attention, register-P, split-K=2 (R11 revert).
//   CTA = 64 hole queries x 1 batch x 1 split. 4 warps, 128 thr,
//   2 CTAs/SM. BK=32, double-buffered K/V.
//   NEW: first 8 of 16 Q A-frags hoisted to registers (32 regs).
// ============================================================
#define SQ_   0          // 32 KB (64 rows x 256 bf16)
#define SK0_  32768      // 16 KB (32 rows)
#define SK1_  49152
#define SV0_  65536
#define SV1_  81920
#define SQN_  98304      // 64 ints
#define ATTN_SMEM 98816  // x2 = 197632 <= 228KB/SM

__device__ __forceinline__ uint32_t sw_addr(int row, int dd) {  // dd multiple of 8
    return (uint32_t)((row * 32 + ((dd >> 3) ^ (row & 7))) << 4);
}

__global__ __launch_bounds__(128, 2)
void k_attn() {
    extern __shared__ char smc[];
    const uint32_t sb = smaddr(smc);
    const int t = threadIdx.x;
    const int lane = t & 31, w = t >> 5;       // w in 0..3
    const int b = blockIdx.y, qt = blockIdx.x, split = blockIdx.z;

    const int nKnown = g_counts[0];
    const int nHole  = g_counts[1];
    const int q0 = qt * 64;
    if (q0 >= nHole) return;
    const int nQ = min(64, nHole - q0);

    const int nkt = (nKnown + 31) >> 5;        // BK=32 tiles
    const int h   = (nkt + 1) >> 1;
    const int kt0 = split ? h : 0;
    const int ktE = split ? nkt : h;
    const int L   = ktE - kt0;

    int* sQn = (int*)(smc + SQN_);
    if (t < 64) sQn[t] = (t < nQ) ? g_qidx[q0 + t] : -1;

    const __nv_bfloat16* gq = g_Q + ((size_t)b * 4096 + q0) * 256;
    const __nv_bfloat16* gk = g_K + (size_t)b * 4096 * 256;
    const __nv_bfloat16* gv = g_V + (size_t)b * 4096 * 256;

    // ---- prologue: Q + KV(kt0) in group0; KV(kt0+1) in group1 ----
#pragma unroll 4
    for (int i = t; i < 2048; i += 128) {   // Q: 64 rows x 32 chunks
        int row = i >> 5, ch = i & 31;
        cpasync16(sb + SQ_ + sw_addr(row, ch << 3), gq + row * 256 + ch * 8);
    }
#define LOAD_KV(kt_, kb_, vb_) do { \
    for (int i2 = t; i2 < 1024; i2 += 128) { \
        int row = i2 >> 5, ch = i2 & 31; \
        uint32_t so = sw_addr(row, ch << 3); \
        cpasync16((kb_) + so, gk + (size_t)((kt_) * 32 + row) * 256 + ch * 8); \
        cpasync16((vb_) + so, gv + (size_t)((kt_) * 32 + row) * 256 + ch * 8); \
    } \
} while (0)

    if (L > 0) { LOAD_KV(kt0, sb + SK0_, sb + SV0_); asm volatile("cp.async.commit_group;"); }
    if (L > 1) { LOAD_KV(kt0 + 1, sb + SK1_, sb + SV1_); asm volatile("cp.async.commit_group;"); }

    float O[32][4];
#pragma unroll
    for (int i = 0; i < 32; ++i) { O[i][0] = O[i][1] = O[i][2] = O[i][3] = 0.f; }
    float rs0 = 0.f, rs1 = 0.f;
    uint32_t aq[8][4];                          // hoisted Q A-frags, ds 0..7

    const int band = w * 16;
    const int r15 = lane & 15, chalf = lane >> 4;   // A-frag mapping
    const int l8 = lane & 7, sel = lane >> 3;       // B-frag mapping

    for (int i = 0; i < L; ++i) {
        const int kt = kt0 + i;
        if (i + 1 < L) asm volatile("cp.async.wait_group 1;" ::: "memory");
        else           asm volatile("cp.async.wait_group 0;" ::: "memory");
        __syncthreads();
        const uint32_t smk = sb + ((i & 1) ? SK1_ : SK0_);
        const uint32_t smv = sb + ((i & 1) ? SV1_ : SV0_);

        if (i == 0) {   // Q resident now; hoist first 8 A-frags
#pragma unroll
            for (int ds = 0; ds < 8; ++ds)
                ldsm4(aq[ds], sb + SQ_ + sw_addr(band + r15, ds * 16 + chalf * 8));
        }

        // ---- S = Q K^T : 16q x 32k ----
        float s[4][4];
#pragma unroll
        for (int j = 0; j < 4; ++j) { s[j][0] = s[j][1] = s[j][2] = s[j][3] = 0.f; }
#pragma unroll
        for (int ds = 0; ds < 16; ++ds) {
            uint32_t a[4];
            const uint32_t* ap;
            if (ds < 8) { ap = aq[ds]; }
            else {
                ldsm4(a, sb + SQ_ + sw_addr(band + r15, ds * 16 + chalf * 8));
                ap = a;
            }
#pragma unroll
            for (int g = 0; g < 2; ++g) {
                uint32_t bb[4];
                ldsm4(bb, smk + sw_addr(g * 16 + (sel >> 1) * 8 + l8, ds * 16 + (sel & 1) * 8));
                mma_bf16(s[2 * g],     ap, bb[0], bb[1]);
                mma_bf16(s[2 * g + 1], ap, bb[2], bb[3]);
            }
        }

        // ---- P = exp(S-1), mask pad keys, repack C-frags -> A-frags ----
        uint32_t pa[2][4];
        const int kg = kt * 32 + (lane & 3) * 2;
#pragma unroll
        for (int j = 0; j < 4; ++j) {
            float p0 = __expf(s[j][0] - 1.f), p1 = __expf(s[j][1] - 1.f);
            float p2 = __expf(s[j][2] - 1.f), p3 = __expf(s[j][3] - 1.f);
            int keyg = kg + j * 8;
            if (keyg >= nKnown)     { p0 = 0.f; p2 = 0.f; }
            if (keyg + 1 >= nKnown) { p1 = 0.f; p3 = 0.f; }
            rs0 += p0 + p1;
            rs1 += p2 + p3;
            pa[j >> 1][(j & 1) * 2]     = packbf2(p0, p1);
            pa[j >> 1][(j & 1) * 2 + 1] = packbf2(p2, p3);
        }

        // ---- O += P V : 16q x 256d ----
#pragma unroll
        for (int ks = 0; ks < 2; ++ks) {
#pragma unroll
            for (int np = 0; np < 16; ++np) {
                uint32_t v[4];
                ldsm4t(v, smv + sw_addr(ks * 16 + (sel & 1) * 8 + l8, np * 16 + (sel >> 1) * 8));
                mma_bf16(O[2 * np],     pa[ks], v[0], v[1]);
                mma_bf16(O[2 * np + 1], pa[ks], v[2], v[3]);
            }
        }

        __syncthreads();   // all warps done reading buffer i&1
        if (i + 2 < L) {
            const uint32_t kb_ = sb + ((i & 1) ? SK1_ : SK0_);
            const uint32_t vb_ = sb + ((i & 1) ? SV1_ : SV0_);
            LOAD_KV(kt + 2, kb_, vb_);
            asm volatile("cp.async.commit_group;");
        }
    }

    // ---- rowsum quad-reduce, write partial L ----
    rs0 += __shfl_xor_sync(0xffffffffu, rs0, 1);
    rs0 += __shfl_xor_sync(0xffffffffu, rs0, 2);
    rs1 += __shfl_xor_sync(0xffffffffu, rs1, 1);
    rs1 += __shfl_xor_sync(0xffffffffu, rs1, 2);
    const int qr0 = band + (lane >> 2), qr1 = qr0 + 8;
    if ((lane & 3) == 0) {
        g_pL[(split * B + b) * 4096 + q0 + qr0] = rs0;
        g_pL[(split * B + b) * 4096 + q0 + qr1] = rs1;
    }

    // ---- transpose O via smem (reuse), coalesced partial store ----
    float* tsO = (float*)smc;    // [256][65] = 66560 B, fits in 98816
#pragma unroll
    for (int nt = 0; nt < 32; ++nt) {
        int d0 = nt * 8 + (lane & 3) * 2;
        tsO[d0 * 65 + qr0]       = O[nt][0];
        tsO[(d0 + 1) * 65 + qr0] = O[nt][1];
        tsO[d0 * 65 + qr1]       = O[nt][2];
        tsO[(d0 + 1) * 65 + qr1] = O[nt][3];
    }
    __syncthreads();
    float* po = g_pO + ((size_t)(split * B + b) * 256) * 4096 + q0;
#pragma unroll 8
    for (int j = 0; j < 128; ++j) {
        int idx = t + 128 * j;
        int q = idx & 63, d = idx >> 6;
        po[(size_t)d * 4096 + q] = tsO[d * 65 + q];
    }
}

// ============================================================
// K5: reduce splits + write the ENTIRE shift channel region.
// ============================================================
__global__ void k_reduce(float* __restrict__ out) {
    const int n = blockIdx.x * 256 + threadIdx.x;
    const int d = blockIdx.y;
    const int b = blockIdx.z;
    const int r = g_rank[n];
    float v = 0.f;
    if (r >= 0) {
        float l = g_pL[b * 4096 + r] + g_pL[(B + b) * 4096 + r];
        float o0 = g_pO[((size_t)b * 256 + d) * 4096 + r];
        float o1 = g_pO[((size_t)(B + b) * 256 + d) * 4096 + r];
        v = (o0 + o1) / l;
    }
    out[((size_t)b * OUTC + 2 * D + d) * N + n] = v;
}

// ============================================================
// Launch order: invnorm, lists, pack, ATTN (4th — the ncu capture
// has consistently profiled the 4th launch; we want k_attn's
// profile next round), then copy (independent) and reduce.
// ============================================================
extern "C" void kernel_launch(void* const* d_in, const int* in_sizes, int n_in,
                              void* d_out, int out_size) {
    const float* x = (const float*)d_in[0];
    const unsigned char* mask = (const unsigned char*)d_in[1];
    float* out = (float*)d_out;
    (void)in_sizes; (void)n_in; (void)out_size;

    k_invnorm<<<dim3(N / 128, B), 128>>>(x);
    k_build_lists<<<1, 256>>>(mask);

    cudaFuncSetAttribute(k_pack, cudaFuncAttributeMaxDynamicSharedMemorySize, PACK_SMEM);
    k_pack<<<dim3(64, B, 3), 256, PACK_SMEM>>>(x);

    cudaFuncSetAttribute(k_attn, cudaFuncAttributeMaxDynamicSharedMemorySize, ATTN_SMEM);
    k_attn<<<dim3(64, B, 2), 128, ATTN_SMEM>>>();

    k_copy<<<(B * C * N / 4) / 256, 256>>>((const float4*)x, (float4*)out);

    k_reduce<<<dim3(N / 256, D, B), 256>>>(out);
}